// round 13
// baseline (speedup 1.0000x reference)
#include <cuda_runtime.h>
#include <cuda_bf16.h>
#include <cuda_fp16.h>
#include <math.h>
#include <stdint.h>

#define BB 8
#define SS 500
#define DD 1024
#define HH 16
#define LL 4
#define FF 4096
#define MM (BB*SS)          // 4000
#define QKVN (3*DD)         // 3072
#define LN_EPS 1e-6f

typedef __half f16;

// ----------------------------------------------------------------------------
// Scratch (device globals; allocation-free)
// ----------------------------------------------------------------------------
__device__ __align__(128) float g_h[(size_t)MM*DD];
__device__ __align__(128) float g_qkv[(size_t)MM*QKVN];
__device__ __align__(128) f16 g_y[(size_t)MM*DD];
__device__ __align__(128) f16 g_o[(size_t)MM*DD];
__device__ __align__(128) f16 g_f[(size_t)MM*FF];
// transposed weights, fp16, layout [N][K]
__device__ __align__(128) f16 g_wqkv[(size_t)LL*QKVN*DD];
__device__ __align__(128) f16 g_wo[(size_t)LL*DD*DD];
__device__ __align__(128) f16 g_w1[(size_t)LL*FF*DD];
__device__ __align__(128) f16 g_w2[(size_t)LL*DD*FF];

// ----------------------------------------------------------------------------
// Helpers
// ----------------------------------------------------------------------------
__device__ __forceinline__ float blk_sum256(float v) {
    __shared__ float sh[8];
    #pragma unroll
    for (int o = 16; o > 0; o >>= 1) v += __shfl_down_sync(0xffffffffu, v, o);
    __syncthreads();
    if ((threadIdx.x & 31) == 0) sh[threadIdx.x >> 5] = v;
    __syncthreads();
    float t = 0.f;
    #pragma unroll
    for (int i = 0; i < 8; i++) t += sh[i];
    return t;
}

__device__ __forceinline__ void cp16(uint32_t dst, const void* src, int sz) {
    asm volatile("cp.async.cg.shared.global [%0], [%1], 16, %2;\n"
                 :: "r"(dst), "l"(src), "r"(sz));
}
__device__ __forceinline__ void cp_commit() { asm volatile("cp.async.commit_group;\n"); }
template<int N> __device__ __forceinline__ void cp_wait() {
    asm volatile("cp.async.wait_group %0;\n" :: "n"(N));
}
__device__ __forceinline__ void mma16816(float* c, const uint32_t* a, const uint32_t* b) {
    asm volatile("mma.sync.aligned.m16n8k16.row.col.f32.f16.f16.f32 "
        "{%0,%1,%2,%3},{%4,%5,%6,%7},{%8,%9},{%0,%1,%2,%3};\n"
        : "+f"(c[0]), "+f"(c[1]), "+f"(c[2]), "+f"(c[3])
        : "r"(a[0]), "r"(a[1]), "r"(a[2]), "r"(a[3]), "r"(b[0]), "r"(b[1]));
}
__device__ __forceinline__ void ldmx4(uint32_t* r, uint32_t addr) {
    asm volatile("ldmatrix.sync.aligned.m8n8.x4.shared.b16 {%0,%1,%2,%3}, [%4];"
        : "=r"(r[0]), "=r"(r[1]), "=r"(r[2]), "=r"(r[3]) : "r"(addr));
}
__device__ __forceinline__ void ldmx4t(uint32_t* r, uint32_t addr) {
    asm volatile("ldmatrix.sync.aligned.m8n8.x4.trans.shared.b16 {%0,%1,%2,%3}, [%4];"
        : "=r"(r[0]), "=r"(r[1]), "=r"(r[2]), "=r"(r[3]) : "r"(addr));
}
__device__ __forceinline__ uint32_t smem_u32(const void* p) {
    uint32_t a;
    asm("{ .reg .u64 t; cvta.to.shared.u64 t, %1; cvt.u32.u64 %0, t; }" : "=r"(a) : "l"(p));
    return a;
}
__device__ __forceinline__ uint32_t pack2h(float a, float b) {
    __half2 p = __floats2half2_rn(a, b);
    return *(uint32_t*)&p;
}
__device__ __forceinline__ void split4(float4 v, uint32_t& hA, uint32_t& hB,
                                       uint32_t& lA, uint32_t& lB) {
    f16 h0 = __float2half_rn(v.x), h1 = __float2half_rn(v.y);
    f16 h2 = __float2half_rn(v.z), h3 = __float2half_rn(v.w);
    __half2 a, b, c, d;
    a.x = h0; a.y = h1; b.x = h2; b.y = h3;
    c.x = __float2half_rn(v.x - __half2float(h0));
    c.y = __float2half_rn(v.y - __half2float(h1));
    d.x = __float2half_rn(v.z - __half2float(h2));
    d.y = __float2half_rn(v.w - __half2float(h3));
    hA = *(uint32_t*)&a; hB = *(uint32_t*)&b;
    lA = *(uint32_t*)&c; lB = *(uint32_t*)&d;
}

// ----------------------------------------------------------------------------
// Embedding + positional encoding
// ----------------------------------------------------------------------------
__global__ void embed_k(const int* __restrict__ x, const float* __restrict__ emb,
                        float* __restrict__ h) {
    int idx = blockIdx.x * blockDim.x + threadIdx.x;
    if (idx >= MM * DD) return;
    int row = idx >> 10, d = idx & 1023;
    int s = row % SS;
    int tok = x[row];
    int i2 = d & ~1;
    float div = expf(-(float)i2 * (logf(10000.0f) / (float)DD));
    float ang = (float)s * div;
    float pe = (d & 1) ? cosf(ang) : sinf(ang);
    h[idx] = emb[(size_t)tok * DD + d] + pe;
}

// ----------------------------------------------------------------------------
// LayerNorm (torch: ddof=1, eps on std)
// ----------------------------------------------------------------------------
__global__ __launch_bounds__(256) void layernorm_k(
    const float* __restrict__ x, const float* __restrict__ a,
    const float* __restrict__ b, float* __restrict__ out) {
    int row = blockIdx.x;
    const float* xp = x + (size_t)row * DD;
    int t4 = threadIdx.x * 4;
    float4 xv = *(const float4*)(xp + t4);
    float mean = blk_sum256(xv.x + xv.y + xv.z + xv.w) * (1.0f / DD);
    float d0 = xv.x - mean, d1 = xv.y - mean, d2 = xv.z - mean, d3 = xv.w - mean;
    float var = blk_sum256(d0*d0 + d1*d1 + d2*d2 + d3*d3) * (1.0f / (DD - 1));
    float inv = 1.0f / (sqrtf(var) + LN_EPS);
    float4 av = *(const float4*)(a + t4);
    float4 bv = *(const float4*)(b + t4);
    float4 r;
    r.x = av.x * d0 * inv + bv.x; r.y = av.y * d1 * inv + bv.y;
    r.z = av.z * d2 * inv + bv.z; r.w = av.w * d3 * inv + bv.w;
    *(float4*)(out + (size_t)row * DD + t4) = r;
}

// LayerNorm -> fp16 output
__global__ __launch_bounds__(256) void ln_h_k(
    const float* __restrict__ x, const float* __restrict__ a,
    const float* __restrict__ b, f16* __restrict__ y) {
    int row = blockIdx.x;
    const float* xp = x + (size_t)row * DD;
    int t4 = threadIdx.x * 4;
    float4 xv = *(const float4*)(xp + t4);
    float mean = blk_sum256(xv.x + xv.y + xv.z + xv.w) * (1.0f / DD);
    float d0 = xv.x - mean, d1 = xv.y - mean, d2 = xv.z - mean, d3 = xv.w - mean;
    float var = blk_sum256(d0*d0 + d1*d1 + d2*d2 + d3*d3) * (1.0f / (DD - 1));
    float inv = 1.0f / (sqrtf(var) + LN_EPS);
    float4 av = *(const float4*)(a + t4);
    float4 bv = *(const float4*)(b + t4);
    uint32_t* py = (uint32_t*)(y + (size_t)row * DD + t4);
    py[0] = pack2h(av.x * d0 * inv + bv.x, av.y * d1 * inv + bv.y);
    py[1] = pack2h(av.z * d2 * inv + bv.z, av.w * d3 * inv + bv.w);
}

// ----------------------------------------------------------------------------
// Merged weight transpose+fp16 convert: ALL matrices, ONE launch.
// ----------------------------------------------------------------------------
#define TILES_PER_LAYER 12288
__global__ void convt_all_k(
    const float* __restrict__ attn_w, const float* __restrict__ w1,
    const float* __restrict__ w2, f16* __restrict__ wq, f16* __restrict__ wo,
    f16* __restrict__ wf1, f16* __restrict__ wf2) {
    __shared__ float t[32][33];
    int id = blockIdx.x;
    int l = id / TILES_PER_LAYER, r = id % TILES_PER_LAYER;
    const float* W; f16* T; int K, N, tt;
    if (r < 3072) {
        int m = r >> 10; tt = r & 1023;
        W = attn_w + ((size_t)(l * 4 + m)) * DD * DD;
        T = wq + ((size_t)(l * 3 + m)) * DD * DD;
        K = DD; N = DD;
    } else if (r < 4096) {
        tt = r - 3072;
        W = attn_w + ((size_t)(l * 4 + 3)) * DD * DD;
        T = wo + (size_t)l * DD * DD;
        K = DD; N = DD;
    } else if (r < 8192) {
        tt = r - 4096;
        W = w1 + (size_t)l * DD * FF;
        T = wf1 + (size_t)l * FF * DD;
        K = DD; N = FF;
    } else {
        tt = r - 8192;
        W = w2 + (size_t)l * FF * DD;
        T = wf2 + (size_t)l * DD * FF;
        K = FF; N = DD;
    }
    int ntx = N >> 5;
    int n0 = (tt % ntx) * 32, k0 = (tt / ntx) * 32;
    int tx = threadIdx.x, ty = threadIdx.y;
    #pragma unroll
    for (int i = ty; i < 32; i += 8) t[i][tx] = W[(size_t)(k0 + i) * N + n0 + tx];
    __syncthreads();
    #pragma unroll
    for (int i = ty; i < 32; i += 8)
        T[(size_t)(n0 + i) * K + k0 + tx] = __float2half_rn(t[tx][i]);
}

// ----------------------------------------------------------------------------
// fp16 GEMM via mma.sync + ldmatrix:  C[M,N] = A[M,K] @ B^T[N,K]
// CTA tile 128(M) x 256(N), 8 warps of 64x64 (2M x 4N), BK=64,
// 3-stage cp.async, 1 CTA/SM (high-register config).
// Stage: A 16KB + B 32KB = 48KB; 3 stages = 144KB.
// MODE 0: Cf = acc+bias | MODE 1: Cf += acc+bias | MODE 2: relu -> fp16
// ----------------------------------------------------------------------------
#define SA_B 0
#define SB_B 16384
#define STAGE_B 49152
#define GEMM_SMEM (3*STAGE_B)

template<int MODE>
__global__ __launch_bounds__(256, 1) void tgemm_k(
    const f16* __restrict__ A, const f16* __restrict__ Bw,
    const float* __restrict__ bias, float* __restrict__ Cf,
    f16* __restrict__ Of,
    int M, int N, int K) {
    extern __shared__ __align__(1024) char smem[];
    const uint32_t sb = smem_u32(smem);
    const int tid = threadIdx.x;
    const int lane = tid & 31, wid = tid >> 5;
    const int wm = wid >> 2, wn = wid & 3;         // warp tile 64(M) x 64(N)
    const int bm = blockIdx.y * 128;
    const int bn = blockIdx.x * 256;
    const int lr = lane & 15, lh = lane >> 4;
    const int g = lane >> 2, tig = lane & 3;

    float acc[4][8][4];
    #pragma unroll
    for (int i = 0; i < 4; i++)
        #pragma unroll
        for (int j = 0; j < 8; j++)
            #pragma unroll
            for (int r = 0; r < 4; r++) acc[i][j][r] = 0.f;

    const int nc = K >> 6;

    // A: 128 rows x 8 u-slots = 1024; B: 256 rows x 8 = 2048 slots.
    #define PF(stg, kof)                                                          \
    {                                                                             \
        uint32_t base = sb + (stg) * STAGE_B;                                     \
        _Pragma("unroll")                                                         \
        for (int j = 0; j < 4; j++) {                                             \
            int idx = tid + 256 * j;                                              \
            int row = idx >> 3, u = idx & 7;                                      \
            uint32_t doff = (uint32_t)(row * 128) + (uint32_t)(((u ^ (row & 7)) << 4)); \
            int gr = bm + row;                                                    \
            int sz = (gr < M) ? 16 : 0;                                           \
            int grc = (gr < M) ? gr : 0;                                          \
            cp16(base + SA_B + doff, A + (size_t)grc * K + (kof) + u * 8, sz);    \
        }                                                                         \
        _Pragma("unroll")                                                         \
        for (int j = 0; j < 8; j++) {                                             \
            int idx = tid + 256 * j;                                              \
            int row = idx >> 3, u = idx & 7;                                      \
            uint32_t doff = (uint32_t)(row * 128) + (uint32_t)(((u ^ (row & 7)) << 4)); \
            cp16(base + SB_B + doff, Bw + (size_t)(bn + row) * K + (kof) + u * 8, 16); \
        }                                                                         \
    }

    PF(0, 0);
    cp_commit();
    if (nc > 1) { PF(1, 64); }
    cp_commit();

    int stg = 0;
    for (int i = 0; i < nc; i++) {
        cp_wait<1>();
        __syncthreads();
        if (i + 2 < nc) {
            int ns = (stg + 2) % 3;
            PF(ns, (i + 2) * 64);
        }
        cp_commit();

        uint32_t base = sb + stg * STAGE_B;
        #pragma unroll
        for (int kq = 0; kq < 4; kq++) {
            uint32_t fa[4][4], fb[4][4];
            #pragma unroll
            for (int mt = 0; mt < 4; mt++) {
                int row = wm * 64 + mt * 16 + lr;
                uint32_t chunk = (uint32_t)(kq * 2 + lh);
                uint32_t off = (uint32_t)(row * 128) + (((chunk ^ (uint32_t)(row & 7)) << 4));
                ldmx4(fa[mt], base + SA_B + off);
            }
            #pragma unroll
            for (int j = 0; j < 4; j++) {
                int row = wn * 64 + j * 16 + lr;
                uint32_t chunk = (uint32_t)(kq * 2 + lh);
                uint32_t off = (uint32_t)(row * 128) + (((chunk ^ (uint32_t)(row & 7)) << 4));
                ldmx4(fb[j], base + SB_B + off);
            }
            #pragma unroll
            for (int mt = 0; mt < 4; mt++)
                #pragma unroll
                for (int nt = 0; nt < 8; nt++) {
                    int j = nt >> 1, sel = nt & 1;
                    uint32_t bb[2] = { fb[j][sel], fb[j][sel + 2] };
                    mma16816(acc[mt][nt], fa[mt], bb);
                }
        }
        stg = (stg + 1) % 3;
    }

    #pragma unroll
    for (int mt = 0; mt < 4; mt++) {
        #pragma unroll
        for (int nt = 0; nt < 8; nt++) {
            int c = bn + wn * 64 + nt * 8 + tig * 2;
            float bx = bias[c], by = bias[c + 1];
            #pragma unroll
            for (int half = 0; half < 2; half++) {
                int r = bm + wm * 64 + mt * 16 + g + half * 8;
                if (r >= M) continue;
                float v0 = acc[mt][nt][half * 2 + 0] + bx;
                float v1 = acc[mt][nt][half * 2 + 1] + by;
                if (MODE == 1) {
                    float2 old = *(float2*)(Cf + (size_t)r * N + c);
                    v0 += old.x; v1 += old.y;
                    float2 o; o.x = v0; o.y = v1;
                    *(float2*)(Cf + (size_t)r * N + c) = o;
                } else if (MODE == 2) {
                    v0 = fmaxf(v0, 0.f); v1 = fmaxf(v1, 0.f);
                    *(uint32_t*)(Of + (size_t)r * N + c) = pack2h(v0, v1);
                } else {
                    float2 o; o.x = v0; o.y = v1;
                    *(float2*)(Cf + (size_t)r * N + c) = o;
                }
            }
        }
    }
    #undef PF
}

// ----------------------------------------------------------------------------
// Fused flash attention (unchanged)
// ----------------------------------------------------------------------------
__global__ __launch_bounds__(128) void flash_k(
    const float* __restrict__ QKV, f16* __restrict__ O) {
    __shared__ __align__(1024) char sm[32768];
    const uint32_t sQV = smem_u32(sm);
    const uint32_t sK  = sQV + 16384;
    const int tid = threadIdx.x, lane = tid & 31, wid = tid >> 5;
    const int lr = lane & 15, lh = lane >> 4;
    const int g = lane >> 2, tig = lane & 3;
    const int bh = blockIdx.y, b = bh >> 4, h = bh & 15;
    const int q0 = blockIdx.x * 64;
    const float* Qg = QKV + (size_t)b * SS * QKVN + h * 64;
    const float* Kg = Qg + DD;
    const float* Vg = Qg + 2 * DD;

    #pragma unroll
    for (int j = 0; j < 8; j++) {
        int slot = tid + 128 * j;
        int row = slot >> 4, c4 = slot & 15;
        int qrow = q0 + row;
        float4 v = make_float4(0.f, 0.f, 0.f, 0.f);
        if (qrow < SS) v = *(const float4*)(Qg + (size_t)qrow * QKVN + c4 * 4);
        uint32_t hA, hB, lA, lB;
        split4(v, hA, hB, lA, lB);
        uint32_t off = (uint32_t)(row * 128) + ((((uint32_t)(c4 >> 1)) ^ (uint32_t)(row & 7)) << 4) + (c4 & 1) * 8;
        *(uint32_t*)(sm + off) = hA;          *(uint32_t*)(sm + off + 4) = hB;
        *(uint32_t*)(sm + 8192 + off) = lA;   *(uint32_t*)(sm + 8192 + off + 4) = lB;
    }
    __syncthreads();

    uint32_t qh[4][4], ql[4][4];
    #pragma unroll
    for (int kq = 0; kq < 4; kq++) {
        int row = wid * 16 + lr;
        uint32_t chunk = (uint32_t)(kq * 2 + lh);
        uint32_t off = (uint32_t)(row * 128) + ((chunk ^ (uint32_t)(row & 7)) << 4);
        ldmx4(qh[kq], sQV + off);
        ldmx4(ql[kq], sQV + 8192 + off);
    }

    float m0 = -1e30f, m1 = -1e30f, l0 = 0.f, l1 = 0.f;
    float ao[8][4];
    #pragma unroll
    for (int j = 0; j < 8; j++)
        #pragma unroll
        for (int r = 0; r < 4; r++) ao[j][r] = 0.f;

    for (int k0 = 0; k0 < SS; k0 += 64) {
        __syncthreads();
        #pragma unroll
        for (int j = 0; j < 8; j++) {
            int slot = tid + 128 * j;
            int row = slot >> 4, c4 = slot & 15;
            int krow = k0 + row;
            float4 kv = make_float4(0.f, 0.f, 0.f, 0.f);
            float4 vv = make_float4(0.f, 0.f, 0.f, 0.f);
            if (krow < SS) {
                kv = *(const float4*)(Kg + (size_t)krow * QKVN + c4 * 4);
                vv = *(const float4*)(Vg + (size_t)krow * QKVN + c4 * 4);
            }
            uint32_t off = (uint32_t)(row * 128) + ((((uint32_t)(c4 >> 1)) ^ (uint32_t)(row & 7)) << 4) + (c4 & 1) * 8;
            uint32_t hA, hB, lA, lB;
            split4(kv, hA, hB, lA, lB);
            *(uint32_t*)(sm + 16384 + off) = hA;  *(uint32_t*)(sm + 16384 + off + 4) = hB;
            *(uint32_t*)(sm + 24576 + off) = lA;  *(uint32_t*)(sm + 24576 + off + 4) = lB;
            split4(vv, hA, hB, lA, lB);
            *(uint32_t*)(sm + off) = hA;          *(uint32_t*)(sm + off + 4) = hB;
            *(uint32_t*)(sm + 8192 + off) = lA;   *(uint32_t*)(sm + 8192 + off + 4) = lB;
        }
        __syncthreads();

        float s[8][4];
        #pragma unroll
        for (int nt = 0; nt < 8; nt++)
            #pragma unroll
            for (int r = 0; r < 4; r++) s[nt][r] = 0.f;
        #pragma unroll
        for (int kq = 0; kq < 4; kq++) {
            uint32_t fkh[4][4], fkl[4][4];
            #pragma unroll
            for (int j2 = 0; j2 < 4; j2++) {
                int row = j2 * 16 + lr;
                uint32_t chunk = (uint32_t)(kq * 2 + lh);
                uint32_t off = (uint32_t)(row * 128) + ((chunk ^ (uint32_t)(row & 7)) << 4);
                ldmx4(fkh[j2], sK + off);
                ldmx4(fkl[j2], sK + 8192 + off);
            }
            #pragma unroll
            for (int nt = 0; nt < 8; nt++) {
                int j2 = nt >> 1, sel = nt & 1;
                uint32_t bhh[2] = { fkh[j2][sel], fkh[j2][sel + 2] };
                uint32_t bll[2] = { fkl[j2][sel], fkl[j2][sel + 2] };
                mma16816(s[nt], qh[kq], bhh);
                mma16816(s[nt], qh[kq], bll);
                mma16816(s[nt], ql[kq], bhh);
            }
        }
        bool tail = (k0 + 64 > SS);
        #pragma unroll
        for (int nt = 0; nt < 8; nt++)
            #pragma unroll
            for (int r = 0; r < 4; r++) {
                s[nt][r] *= 0.125f;
                if (tail && (k0 + nt * 8 + tig * 2 + (r & 1)) >= SS) s[nt][r] = -1e30f;
            }
        float mx0 = -1e30f, mx1 = -1e30f;
        #pragma unroll
        for (int nt = 0; nt < 8; nt++) {
            mx0 = fmaxf(mx0, fmaxf(s[nt][0], s[nt][1]));
            mx1 = fmaxf(mx1, fmaxf(s[nt][2], s[nt][3]));
        }
        mx0 = fmaxf(mx0, __shfl_xor_sync(0xffffffffu, mx0, 1));
        mx0 = fmaxf(mx0, __shfl_xor_sync(0xffffffffu, mx0, 2));
        mx1 = fmaxf(mx1, __shfl_xor_sync(0xffffffffu, mx1, 1));
        mx1 = fmaxf(mx1, __shfl_xor_sync(0xffffffffu, mx1, 2));
        float mn0 = fmaxf(m0, mx0), mn1 = fmaxf(m1, mx1);
        float sc0 = __expf(m0 - mn0), sc1 = __expf(m1 - mn1);
        m0 = mn0; m1 = mn1;
        float rs0 = 0.f, rs1 = 0.f;
        #pragma unroll
        for (int nt = 0; nt < 8; nt++) {
            s[nt][0] = __expf(s[nt][0] - m0); rs0 += s[nt][0];
            s[nt][1] = __expf(s[nt][1] - m0); rs0 += s[nt][1];
            s[nt][2] = __expf(s[nt][2] - m1); rs1 += s[nt][2];
            s[nt][3] = __expf(s[nt][3] - m1); rs1 += s[nt][3];
        }
        rs0 += __shfl_xor_sync(0xffffffffu, rs0, 1);
        rs0 += __shfl_xor_sync(0xffffffffu, rs0, 2);
        rs1 += __shfl_xor_sync(0xffffffffu, rs1, 1);
        rs1 += __shfl_xor_sync(0xffffffffu, rs1, 2);
        l0 = l0 * sc0 + rs0; l1 = l1 * sc1 + rs1;
        #pragma unroll
        for (int j = 0; j < 8; j++) {
            ao[j][0] *= sc0; ao[j][1] *= sc0;
            ao[j][2] *= sc1; ao[j][3] *= sc1;
        }
        #pragma unroll
        for (int kc = 0; kc < 4; kc++) {
            uint32_t pa[4] = {
                pack2h(s[2*kc][0],   s[2*kc][1]),
                pack2h(s[2*kc][2],   s[2*kc][3]),
                pack2h(s[2*kc+1][0], s[2*kc+1][1]),
                pack2h(s[2*kc+1][2], s[2*kc+1][3]) };
            int vrow = kc * 16 + (lane & 7) + ((lane & 8) ? 8 : 0);
            #pragma unroll
            for (int dp = 0; dp < 4; dp++) {
                uint32_t u = (uint32_t)(dp * 2 + ((lane & 16) ? 1 : 0));
                uint32_t off = (uint32_t)(vrow * 128) + ((u ^ (uint32_t)(vrow & 7)) << 4);
                uint32_t fvh[4], fvl[4];
                ldmx4t(fvh, sQV + off);
                ldmx4t(fvl, sQV + 8192 + off);
                uint32_t b0h[2] = { fvh[0], fvh[1] }, b1h[2] = { fvh[2], fvh[3] };
                uint32_t b0l[2] = { fvl[0], fvl[1] }, b1l[2] = { fvl[2], fvl[3] };
                mma16816(ao[dp*2],     pa, b0h);
                mma16816(ao[dp*2],     pa, b0l);
                mma16816(ao[dp*2 + 1], pa, b1h);
                mma16816(ao[dp*2 + 1], pa, b1l);
            }
        }
    }

    float il0 = 1.f / l0, il1 = 1.f / l1;
    int r0 = q0 + wid * 16 + g, r1 = r0 + 8;
    #pragma unroll
    for (int j = 0; j < 8; j++) {
        int d = h * 64 + j * 8 + tig * 2;
        if (r0 < SS)
            *(uint32_t*)(O + (size_t)(b * SS + r0) * DD + d) = pack2h(ao[j][0] * il0, ao[j][1] * il0);
        if (r1 < SS)
            *(uint32_t*)(O + (size_t)(b * SS + r1) * DD + d) = pack2h(ao[j][2] * il1, ao[j][3] * il1);
    }
}

// ----------------------------------------------------------------------------
// Host orchestration
// ----------------------------------------------------------------------------
extern "C" void kernel_launch(void* const* d_in, const int* in_sizes, int n_in,
                              void* d_out, int out_size) {
    const int*   x      = (const int*)d_in[0];
    const float* emb    = (const float*)d_in[1];
    const float* attn_w = (const float*)d_in[2];
    const float* attn_b = (const float*)d_in[3];
    const float* ln_a   = (const float*)d_in[4];
    const float* ln_b   = (const float*)d_in[5];
    const float* w1     = (const float*)d_in[6];
    const float* b1     = (const float*)d_in[7];
    const float* w2     = (const float*)d_in[8];
    const float* b2     = (const float*)d_in[9];
    const float* na     = (const float*)d_in[10];
    const float* nb     = (const float*)d_in[11];
    float* out = (float*)d_out;

    float *h, *qkv;
    f16 *y, *o, *f;
    f16 *wq, *wo, *wf1, *wf2;
    cudaGetSymbolAddress((void**)&h, g_h);
    cudaGetSymbolAddress((void**)&qkv, g_qkv);
    cudaGetSymbolAddress((void**)&y, g_y);
    cudaGetSymbolAddress((void**)&o, g_o);
    cudaGetSymbolAddress((void**)&f, g_f);
    cudaGetSymbolAddress((void**)&wq, g_wqkv);
    cudaGetSymbolAddress((void**)&wo, g_wo);
    cudaGetSymbolAddress((void**)&wf1, g_w1);
    cudaGetSymbolAddress((void**)&wf2, g_w2);

    cudaFuncSetAttribute(tgemm_k<0>, cudaFuncAttributeMaxDynamicSharedMemorySize, GEMM_SMEM);
    cudaFuncSetAttribute(tgemm_k<1>, cudaFuncAttributeMaxDynamicSharedMemorySize, GEMM_SMEM);
    cudaFuncSetAttribute(tgemm_k<2>, cudaFuncAttributeMaxDynamicSharedMemorySize, GEMM_SMEM);

    dim3 cb(32, 8);
    convt_all_k<<<LL * TILES_PER_LAYER, cb>>>(attn_w, w1, w2, wq, wo, wf1, wf2);
    embed_k<<<(MM * DD + 255) / 256, 256>>>(x, emb, h);

    dim3 gQKV(QKVN / 256, (MM + 127) / 128);   // (12, 32)
    dim3 gD(DD / 256, (MM + 127) / 128);       // (4, 32)
    dim3 gF(FF / 256, (MM + 127) / 128);       // (16, 32)
    dim3 gFA(8, BB * HH);

    for (int l = 0; l < LL; l++) {
        const float* Wb = attn_b + (size_t)l * 4 * DD;
        const float* la = ln_a + (size_t)l * 2 * DD;
        const float* lb = ln_b + (size_t)l * 2 * DD;

        // attention sublayer (launch #6 of the graph = tgemm<1> for ncu)
        ln_h_k<<<MM, 256>>>(h, la, lb, y);
        tgemm_k<0><<<gQKV, 256, GEMM_SMEM>>>(y,
            wq + (size_t)l*QKVN*DD, Wb, qkv, nullptr, MM, QKVN, DD);
        flash_k<<<gFA, 128>>>(qkv, o);
        tgemm_k<1><<<gD, 256, GEMM_SMEM>>>(o,
            wo + (size_t)l*DD*DD, Wb + 3*DD, h, nullptr, MM, DD, DD);

        // feed-forward sublayer
        ln_h_k<<<MM, 256>>>(h, la + DD, lb + DD, y);
        tgemm_k<2><<<gF, 256, GEMM_SMEM>>>(y,
            wf1 + (size_t)l*FF*DD, b1 + (size_t)l*FF, nullptr, f, MM, FF, DD);
        tgemm_k<1><<<gD, 256, GEMM_SMEM>>>(f,
            wf2 + (size_t)l*DD*FF, b2 + (size_t)l*DD, h, nullptr, MM, DD, FF);
    }

    layernorm_k<<<MM, 256>>>(h, na, nb, out);
}

// round 14
// speedup vs baseline: 1.1157x; 1.1157x over previous
#include <cuda_runtime.h>
#include <cuda_bf16.h>
#include <cuda_fp16.h>
#include <math.h>
#include <stdint.h>

#define BB 8
#define SS 500
#define DD 1024
#define HH 16
#define LL 4
#define FF 4096
#define MM (BB*SS)          // 4000
#define QKVN (3*DD)         // 3072
#define LN_EPS 1e-6f

typedef __half f16;

// ----------------------------------------------------------------------------
// Scratch (device globals; allocation-free)
// ----------------------------------------------------------------------------
__device__ __align__(128) float g_h[(size_t)MM*DD];
__device__ __align__(128) f16 g_qkvh[(size_t)MM*QKVN];
__device__ __align__(128) f16 g_qkvl[(size_t)MM*QKVN];
__device__ __align__(128) f16 g_y[(size_t)MM*DD];
__device__ __align__(128) f16 g_o[(size_t)MM*DD];
__device__ __align__(128) f16 g_f[(size_t)MM*FF];
// transposed weights, fp16, layout [N][K]
__device__ __align__(128) f16 g_wqkv[(size_t)LL*QKVN*DD];
__device__ __align__(128) f16 g_wo[(size_t)LL*DD*DD];
__device__ __align__(128) f16 g_w1[(size_t)LL*FF*DD];
__device__ __align__(128) f16 g_w2[(size_t)LL*DD*FF];

// ----------------------------------------------------------------------------
// Helpers
// ----------------------------------------------------------------------------
__device__ __forceinline__ float blk_sum256(float v) {
    __shared__ float sh[8];
    #pragma unroll
    for (int o = 16; o > 0; o >>= 1) v += __shfl_down_sync(0xffffffffu, v, o);
    __syncthreads();
    if ((threadIdx.x & 31) == 0) sh[threadIdx.x >> 5] = v;
    __syncthreads();
    float t = 0.f;
    #pragma unroll
    for (int i = 0; i < 8; i++) t += sh[i];
    return t;
}

__device__ __forceinline__ void cp16(uint32_t dst, const void* src, int sz) {
    asm volatile("cp.async.cg.shared.global [%0], [%1], 16, %2;\n"
                 :: "r"(dst), "l"(src), "r"(sz));
}
__device__ __forceinline__ void cp_commit() { asm volatile("cp.async.commit_group;\n"); }
template<int N> __device__ __forceinline__ void cp_wait() {
    asm volatile("cp.async.wait_group %0;\n" :: "n"(N));
}
__device__ __forceinline__ void mma16816(float* c, const uint32_t* a, const uint32_t* b) {
    asm volatile("mma.sync.aligned.m16n8k16.row.col.f32.f16.f16.f32 "
        "{%0,%1,%2,%3},{%4,%5,%6,%7},{%8,%9},{%0,%1,%2,%3};\n"
        : "+f"(c[0]), "+f"(c[1]), "+f"(c[2]), "+f"(c[3])
        : "r"(a[0]), "r"(a[1]), "r"(a[2]), "r"(a[3]), "r"(b[0]), "r"(b[1]));
}
__device__ __forceinline__ void ldmx4(uint32_t* r, uint32_t addr) {
    asm volatile("ldmatrix.sync.aligned.m8n8.x4.shared.b16 {%0,%1,%2,%3}, [%4];"
        : "=r"(r[0]), "=r"(r[1]), "=r"(r[2]), "=r"(r[3]) : "r"(addr));
}
__device__ __forceinline__ void ldmx4t(uint32_t* r, uint32_t addr) {
    asm volatile("ldmatrix.sync.aligned.m8n8.x4.trans.shared.b16 {%0,%1,%2,%3}, [%4];"
        : "=r"(r[0]), "=r"(r[1]), "=r"(r[2]), "=r"(r[3]) : "r"(addr));
}
__device__ __forceinline__ uint32_t smem_u32(const void* p) {
    uint32_t a;
    asm("{ .reg .u64 t; cvta.to.shared.u64 t, %1; cvt.u32.u64 %0, t; }" : "=r"(a) : "l"(p));
    return a;
}
__device__ __forceinline__ uint32_t pack2h(float a, float b) {
    __half2 p = __floats2half2_rn(a, b);
    return *(uint32_t*)&p;
}
__device__ __forceinline__ void split_pair(float v0, float v1, uint32_t& hw, uint32_t& lw) {
    f16 h0 = __float2half_rn(v0), h1 = __float2half_rn(v1);
    __half2 hh, ll;
    hh.x = h0; hh.y = h1;
    ll.x = __float2half_rn(v0 - __half2float(h0));
    ll.y = __float2half_rn(v1 - __half2float(h1));
    hw = *(uint32_t*)&hh; lw = *(uint32_t*)&ll;
}

// ----------------------------------------------------------------------------
// Embedding + positional encoding
// ----------------------------------------------------------------------------
__global__ void embed_k(const int* __restrict__ x, const float* __restrict__ emb,
                        float* __restrict__ h) {
    int idx = blockIdx.x * blockDim.x + threadIdx.x;
    if (idx >= MM * DD) return;
    int row = idx >> 10, d = idx & 1023;
    int s = row % SS;
    int tok = x[row];
    int i2 = d & ~1;
    float div = expf(-(float)i2 * (logf(10000.0f) / (float)DD));
    float ang = (float)s * div;
    float pe = (d & 1) ? cosf(ang) : sinf(ang);
    h[idx] = emb[(size_t)tok * DD + d] + pe;
}

// ----------------------------------------------------------------------------
// LayerNorm (torch: ddof=1, eps on std)
// ----------------------------------------------------------------------------
__global__ __launch_bounds__(256) void layernorm_k(
    const float* __restrict__ x, const float* __restrict__ a,
    const float* __restrict__ b, float* __restrict__ out) {
    int row = blockIdx.x;
    const float* xp = x + (size_t)row * DD;
    int t4 = threadIdx.x * 4;
    float4 xv = *(const float4*)(xp + t4);
    float mean = blk_sum256(xv.x + xv.y + xv.z + xv.w) * (1.0f / DD);
    float d0 = xv.x - mean, d1 = xv.y - mean, d2 = xv.z - mean, d3 = xv.w - mean;
    float var = blk_sum256(d0*d0 + d1*d1 + d2*d2 + d3*d3) * (1.0f / (DD - 1));
    float inv = 1.0f / (sqrtf(var) + LN_EPS);
    float4 av = *(const float4*)(a + t4);
    float4 bv = *(const float4*)(b + t4);
    float4 r;
    r.x = av.x * d0 * inv + bv.x; r.y = av.y * d1 * inv + bv.y;
    r.z = av.z * d2 * inv + bv.z; r.w = av.w * d3 * inv + bv.w;
    *(float4*)(out + (size_t)row * DD + t4) = r;
}

// LayerNorm -> fp16 output
__global__ __launch_bounds__(256) void ln_h_k(
    const float* __restrict__ x, const float* __restrict__ a,
    const float* __restrict__ b, f16* __restrict__ y) {
    int row = blockIdx.x;
    const float* xp = x + (size_t)row * DD;
    int t4 = threadIdx.x * 4;
    float4 xv = *(const float4*)(xp + t4);
    float mean = blk_sum256(xv.x + xv.y + xv.z + xv.w) * (1.0f / DD);
    float d0 = xv.x - mean, d1 = xv.y - mean, d2 = xv.z - mean, d3 = xv.w - mean;
    float var = blk_sum256(d0*d0 + d1*d1 + d2*d2 + d3*d3) * (1.0f / (DD - 1));
    float inv = 1.0f / (sqrtf(var) + LN_EPS);
    float4 av = *(const float4*)(a + t4);
    float4 bv = *(const float4*)(b + t4);
    uint32_t* py = (uint32_t*)(y + (size_t)row * DD + t4);
    py[0] = pack2h(av.x * d0 * inv + bv.x, av.y * d1 * inv + bv.y);
    py[1] = pack2h(av.z * d2 * inv + bv.z, av.w * d3 * inv + bv.w);
}

// ----------------------------------------------------------------------------
// Merged weight transpose+fp16 convert: ALL matrices, ONE launch.
// ----------------------------------------------------------------------------
#define TILES_PER_LAYER 12288
__global__ void convt_all_k(
    const float* __restrict__ attn_w, const float* __restrict__ w1,
    const float* __restrict__ w2, f16* __restrict__ wq, f16* __restrict__ wo,
    f16* __restrict__ wf1, f16* __restrict__ wf2) {
    __shared__ float t[32][33];
    int id = blockIdx.x;
    int l = id / TILES_PER_LAYER, r = id % TILES_PER_LAYER;
    const float* W; f16* T; int K, N, tt;
    if (r < 3072) {
        int m = r >> 10; tt = r & 1023;
        W = attn_w + ((size_t)(l * 4 + m)) * DD * DD;
        T = wq + ((size_t)(l * 3 + m)) * DD * DD;
        K = DD; N = DD;
    } else if (r < 4096) {
        tt = r - 3072;
        W = attn_w + ((size_t)(l * 4 + 3)) * DD * DD;
        T = wo + (size_t)l * DD * DD;
        K = DD; N = DD;
    } else if (r < 8192) {
        tt = r - 4096;
        W = w1 + (size_t)l * DD * FF;
        T = wf1 + (size_t)l * FF * DD;
        K = DD; N = FF;
    } else {
        tt = r - 8192;
        W = w2 + (size_t)l * FF * DD;
        T = wf2 + (size_t)l * DD * FF;
        K = FF; N = DD;
    }
    int ntx = N >> 5;
    int n0 = (tt % ntx) * 32, k0 = (tt / ntx) * 32;
    int tx = threadIdx.x, ty = threadIdx.y;
    #pragma unroll
    for (int i = ty; i < 32; i += 8) t[i][tx] = W[(size_t)(k0 + i) * N + n0 + tx];
    __syncthreads();
    #pragma unroll
    for (int i = ty; i < 32; i += 8)
        T[(size_t)(n0 + i) * K + k0 + tx] = __float2half_rn(t[tx][i]);
}

// ----------------------------------------------------------------------------
// fp16 GEMM via mma.sync + ldmatrix (R11 config: 128x128 CTA, 8 warps of 32x64,
// BK=64, 3-stage cp.async, 2 CTAs/SM).
// MODE 0: split(acc+bias) -> f16 hi/lo (Oh, Ol)       [QKV]
// MODE 1: Cf += acc+bias                               [residual]
// MODE 2: relu(acc+bias) -> f16 (Oh)                   [FFN1]
// ----------------------------------------------------------------------------
#define SA_B 0
#define SB_B 16384
#define STAGE_B 32768
#define GEMM_SMEM (3*STAGE_B)

template<int MODE>
__global__ __launch_bounds__(256) void tgemm_k(
    const f16* __restrict__ A, const f16* __restrict__ Bw,
    const float* __restrict__ bias, float* __restrict__ Cf,
    f16* __restrict__ Oh, f16* __restrict__ Ol,
    int M, int N, int K) {
    extern __shared__ __align__(1024) char smem[];
    const uint32_t sb = smem_u32(smem);
    const int tid = threadIdx.x;
    const int lane = tid & 31, wid = tid >> 5;
    const int wm = wid >> 1, wn = wid & 1;
    const int bm = blockIdx.y * 128;
    const int bn = blockIdx.x * 128;
    const int lr = lane & 15, lh = lane >> 4;
    const int g = lane >> 2, tig = lane & 3;

    float acc[2][8][4];
    #pragma unroll
    for (int i = 0; i < 2; i++)
        #pragma unroll
        for (int j = 0; j < 8; j++)
            #pragma unroll
            for (int r = 0; r < 4; r++) acc[i][j][r] = 0.f;

    const int nc = K >> 6;

    #define PF(stg, kof)                                                          \
    {                                                                             \
        uint32_t base = sb + (stg) * STAGE_B;                                     \
        _Pragma("unroll")                                                         \
        for (int j = 0; j < 4; j++) {                                             \
            int idx = tid + 256 * j;                                              \
            int row = idx >> 3, u = idx & 7;                                      \
            uint32_t doff = (uint32_t)(row * 128) + (uint32_t)(((u ^ (row & 7)) << 4)); \
            int gr = bm + row;                                                    \
            int sz = (gr < M) ? 16 : 0;                                           \
            int grc = (gr < M) ? gr : 0;                                          \
            cp16(base + SA_B + doff, A + (size_t)grc * K + (kof) + u * 8, sz);    \
            int gn = bn + row;                                                    \
            cp16(base + SB_B + doff, Bw + (size_t)gn * K + (kof) + u * 8, 16);    \
        }                                                                         \
    }

    PF(0, 0);
    cp_commit();
    if (nc > 1) { PF(1, 64); }
    cp_commit();

    int stg = 0;
    for (int i = 0; i < nc; i++) {
        cp_wait<1>();
        __syncthreads();
        if (i + 2 < nc) {
            int ns = (stg + 2) % 3;
            PF(ns, (i + 2) * 64);
        }
        cp_commit();

        uint32_t base = sb + stg * STAGE_B;
        #pragma unroll
        for (int kq = 0; kq < 4; kq++) {
            uint32_t fa[2][4], fb[4][4];
            #pragma unroll
            for (int mt = 0; mt < 2; mt++) {
                int row = wm * 32 + mt * 16 + lr;
                uint32_t chunk = (uint32_t)(kq * 2 + lh);
                uint32_t off = (uint32_t)(row * 128) + (((chunk ^ (uint32_t)(row & 7)) << 4));
                ldmx4(fa[mt], base + SA_B + off);
            }
            #pragma unroll
            for (int j = 0; j < 4; j++) {
                int row = wn * 64 + j * 16 + lr;
                uint32_t chunk = (uint32_t)(kq * 2 + lh);
                uint32_t off = (uint32_t)(row * 128) + (((chunk ^ (uint32_t)(row & 7)) << 4));
                ldmx4(fb[j], base + SB_B + off);
            }
            #pragma unroll
            for (int mt = 0; mt < 2; mt++)
                #pragma unroll
                for (int nt = 0; nt < 8; nt++) {
                    int j = nt >> 1, sel = nt & 1;
                    uint32_t bb[2] = { fb[j][sel], fb[j][sel + 2] };
                    mma16816(acc[mt][nt], fa[mt], bb);
                }
        }
        stg = (stg + 1) % 3;
    }

    #pragma unroll
    for (int mt = 0; mt < 2; mt++) {
        #pragma unroll
        for (int nt = 0; nt < 8; nt++) {
            int c = bn + wn * 64 + nt * 8 + tig * 2;
            float bx = bias[c], by = bias[c + 1];
            #pragma unroll
            for (int half = 0; half < 2; half++) {
                int r = bm + wm * 32 + mt * 16 + g + half * 8;
                if (r >= M) continue;
                float v0 = acc[mt][nt][half * 2 + 0] + bx;
                float v1 = acc[mt][nt][half * 2 + 1] + by;
                if (MODE == 1) {
                    float2 old = *(float2*)(Cf + (size_t)r * N + c);
                    v0 += old.x; v1 += old.y;
                    float2 o; o.x = v0; o.y = v1;
                    *(float2*)(Cf + (size_t)r * N + c) = o;
                } else if (MODE == 2) {
                    v0 = fmaxf(v0, 0.f); v1 = fmaxf(v1, 0.f);
                    *(uint32_t*)(Oh + (size_t)r * N + c) = pack2h(v0, v1);
                } else {
                    uint32_t hw, lw;
                    split_pair(v0, v1, hw, lw);
                    *(uint32_t*)(Oh + (size_t)r * N + c) = hw;
                    *(uint32_t*)(Ol + (size_t)r * N + c) = lw;
                }
            }
        }
    }
    #undef PF
}

// ----------------------------------------------------------------------------
// Fused flash attention v2: Q/K/V already fp16 hi/lo in gmem; cp.async loads,
// 2-stage K/V pipeline. Per CTA one (b,h) x 64-q tile, 128 threads.
// Dyn smem 80KB: Qh@0, Ql@8192, stage s@16384+s*32768: Kh,Kl,Vh,Vl (8KB each).
// ----------------------------------------------------------------------------
#define FL_SMEM (16384 + 2*32768)

__global__ __launch_bounds__(128) void flash_k(
    const f16* __restrict__ QKVh, const f16* __restrict__ QKVl,
    f16* __restrict__ O) {
    extern __shared__ __align__(1024) char sm[];
    const uint32_t sbase = smem_u32(sm);
    const int tid = threadIdx.x, lane = tid & 31, wid = tid >> 5;
    const int lr = lane & 15, lh = lane >> 4;
    const int g = lane >> 2, tig = lane & 3;
    const int bh = blockIdx.y, b = bh >> 4, h = bh & 15;
    const int q0 = blockIdx.x * 64;
    const f16* Qhp = QKVh + (size_t)b * SS * QKVN + h * 64;
    const f16* Qlp = QKVl + (size_t)b * SS * QKVN + h * 64;

    // Q tiles (hi/lo): 2 arrays x 512 chunks
    #pragma unroll
    for (int j = 0; j < 4; j++) {
        int idx = tid + 128 * j;
        int row = idx >> 3, u = idx & 7;
        uint32_t off = (uint32_t)(row * 128) + (((uint32_t)(u ^ (row & 7))) << 4);
        int qrow = q0 + row;
        int sz = (qrow < SS) ? 16 : 0;
        int qr = (qrow < SS) ? qrow : 0;
        cp16(sbase + off,        Qhp + (size_t)qr * QKVN + u * 8, sz);
        cp16(sbase + 8192 + off, Qlp + (size_t)qr * QKVN + u * 8, sz);
    }

    // K/V prefetch macro: stage s, k-tile base kt
    #define PFKV(s, kt)                                                            \
    {                                                                              \
        uint32_t stb = sbase + 16384 + (s) * 32768;                                \
        _Pragma("unroll")                                                          \
        for (int j = 0; j < 4; j++) {                                              \
            int idx = tid + 128 * j;                                               \
            int row = idx >> 3, u = idx & 7;                                       \
            uint32_t off = (uint32_t)(row * 128) + (((uint32_t)(u ^ (row & 7))) << 4); \
            int krow = (kt) + row;                                                 \
            int sz = (krow < SS) ? 16 : 0;                                         \
            int kr = (krow < SS) ? krow : 0;                                       \
            const f16* kh = Qhp + DD + (size_t)kr * QKVN + u * 8;                  \
            const f16* kl = Qlp + DD + (size_t)kr * QKVN + u * 8;                  \
            const f16* vh = Qhp + 2 * DD + (size_t)kr * QKVN + u * 8;              \
            const f16* vl = Qlp + 2 * DD + (size_t)kr * QKVN + u * 8;              \
            cp16(stb + off, kh, sz);                                               \
            cp16(stb + 8192 + off, kl, sz);                                        \
            cp16(stb + 16384 + off, vh, sz);                                       \
            cp16(stb + 24576 + off, vl, sz);                                       \
        }                                                                          \
    }

    PFKV(0, 0);
    cp_commit();

    uint32_t qh[4][4], ql[4][4];
    float m0 = -1e30f, m1 = -1e30f, l0 = 0.f, l1 = 0.f;
    float ao[8][4];
    #pragma unroll
    for (int j = 0; j < 8; j++)
        #pragma unroll
        for (int r = 0; r < 4; r++) ao[j][r] = 0.f;

    const int nt8 = (SS + 63) / 64;   // 8
    for (int t = 0; t < nt8; t++) {
        cp_wait<0>();
        __syncthreads();
        if (t == 0) {
            #pragma unroll
            for (int kq = 0; kq < 4; kq++) {
                int row = wid * 16 + lr;
                uint32_t chunk = (uint32_t)(kq * 2 + lh);
                uint32_t off = (uint32_t)(row * 128) + ((chunk ^ (uint32_t)(row & 7)) << 4);
                ldmx4(qh[kq], sbase + off);
                ldmx4(ql[kq], sbase + 8192 + off);
            }
        }
        if (t + 1 < nt8) { PFKV((t + 1) & 1, (t + 1) * 64); cp_commit(); }

        uint32_t stb = sbase + 16384 + (t & 1) * 32768;
        int k0 = t * 64;

        float s[8][4];
        #pragma unroll
        for (int nt = 0; nt < 8; nt++)
            #pragma unroll
            for (int r = 0; r < 4; r++) s[nt][r] = 0.f;
        #pragma unroll
        for (int kq = 0; kq < 4; kq++) {
            uint32_t fkh[4][4], fkl[4][4];
            #pragma unroll
            for (int j2 = 0; j2 < 4; j2++) {
                int row = j2 * 16 + lr;
                uint32_t chunk = (uint32_t)(kq * 2 + lh);
                uint32_t off = (uint32_t)(row * 128) + ((chunk ^ (uint32_t)(row & 7)) << 4);
                ldmx4(fkh[j2], stb + off);
                ldmx4(fkl[j2], stb + 8192 + off);
            }
            #pragma unroll
            for (int nt = 0; nt < 8; nt++) {
                int j2 = nt >> 1, sel = nt & 1;
                uint32_t bhh[2] = { fkh[j2][sel], fkh[j2][sel + 2] };
                uint32_t bll[2] = { fkl[j2][sel], fkl[j2][sel + 2] };
                mma16816(s[nt], qh[kq], bhh);
                mma16816(s[nt], qh[kq], bll);
                mma16816(s[nt], ql[kq], bhh);
            }
        }
        bool tail = (k0 + 64 > SS);
        #pragma unroll
        for (int nt = 0; nt < 8; nt++)
            #pragma unroll
            for (int r = 0; r < 4; r++) {
                s[nt][r] *= 0.125f;
                if (tail && (k0 + nt * 8 + tig * 2 + (r & 1)) >= SS) s[nt][r] = -1e30f;
            }
        float mx0 = -1e30f, mx1 = -1e30f;
        #pragma unroll
        for (int nt = 0; nt < 8; nt++) {
            mx0 = fmaxf(mx0, fmaxf(s[nt][0], s[nt][1]));
            mx1 = fmaxf(mx1, fmaxf(s[nt][2], s[nt][3]));
        }
        mx0 = fmaxf(mx0, __shfl_xor_sync(0xffffffffu, mx0, 1));
        mx0 = fmaxf(mx0, __shfl_xor_sync(0xffffffffu, mx0, 2));
        mx1 = fmaxf(mx1, __shfl_xor_sync(0xffffffffu, mx1, 1));
        mx1 = fmaxf(mx1, __shfl_xor_sync(0xffffffffu, mx1, 2));
        float mn0 = fmaxf(m0, mx0), mn1 = fmaxf(m1, mx1);
        float sc0 = __expf(m0 - mn0), sc1 = __expf(m1 - mn1);
        m0 = mn0; m1 = mn1;
        float rs0 = 0.f, rs1 = 0.f;
        #pragma unroll
        for (int nt = 0; nt < 8; nt++) {
            s[nt][0] = __expf(s[nt][0] - m0); rs0 += s[nt][0];
            s[nt][1] = __expf(s[nt][1] - m0); rs0 += s[nt][1];
            s[nt][2] = __expf(s[nt][2] - m1); rs1 += s[nt][2];
            s[nt][3] = __expf(s[nt][3] - m1); rs1 += s[nt][3];
        }
        rs0 += __shfl_xor_sync(0xffffffffu, rs0, 1);
        rs0 += __shfl_xor_sync(0xffffffffu, rs0, 2);
        rs1 += __shfl_xor_sync(0xffffffffu, rs1, 1);
        rs1 += __shfl_xor_sync(0xffffffffu, rs1, 2);
        l0 = l0 * sc0 + rs0; l1 = l1 * sc1 + rs1;
        #pragma unroll
        for (int j = 0; j < 8; j++) {
            ao[j][0] *= sc0; ao[j][1] *= sc0;
            ao[j][2] *= sc1; ao[j][3] *= sc1;
        }
        #pragma unroll
        for (int kc = 0; kc < 4; kc++) {
            uint32_t pa[4] = {
                pack2h(s[2*kc][0],   s[2*kc][1]),
                pack2h(s[2*kc][2],   s[2*kc][3]),
                pack2h(s[2*kc+1][0], s[2*kc+1][1]),
                pack2h(s[2*kc+1][2], s[2*kc+1][3]) };
            int vrow = kc * 16 + (lane & 7) + ((lane & 8) ? 8 : 0);
            #pragma unroll
            for (int dp = 0; dp < 4; dp++) {
                uint32_t u = (uint32_t)(dp * 2 + ((lane & 16) ? 1 : 0));
                uint32_t off = (uint32_t)(vrow * 128) + ((u ^ (uint32_t)(vrow & 7)) << 4);
                uint32_t fvh[4], fvl[4];
                ldmx4t(fvh, stb + 16384 + off);
                ldmx4t(fvl, stb + 24576 + off);
                uint32_t b0h[2] = { fvh[0], fvh[1] }, b1h[2] = { fvh[2], fvh[3] };
                uint32_t b0l[2] = { fvl[0], fvl[1] }, b1l[2] = { fvl[2], fvl[3] };
                mma16816(ao[dp*2],     pa, b0h);
                mma16816(ao[dp*2],     pa, b0l);
                mma16816(ao[dp*2 + 1], pa, b1h);
                mma16816(ao[dp*2 + 1], pa, b1l);
            }
        }
    }
    #undef PFKV

    float il0 = 1.f / l0, il1 = 1.f / l1;
    int r0 = q0 + wid * 16 + g, r1 = r0 + 8;
    #pragma unroll
    for (int j = 0; j < 8; j++) {
        int d = h * 64 + j * 8 + tig * 2;
        if (r0 < SS)
            *(uint32_t*)(O + (size_t)(b * SS + r0) * DD + d) = pack2h(ao[j][0] * il0, ao[j][1] * il0);
        if (r1 < SS)
            *(uint32_t*)(O + (size_t)(b * SS + r1) * DD + d) = pack2h(ao[j][2] * il1, ao[j][3] * il1);
    }
}

// ----------------------------------------------------------------------------
// Host orchestration
// ----------------------------------------------------------------------------
extern "C" void kernel_launch(void* const* d_in, const int* in_sizes, int n_in,
                              void* d_out, int out_size) {
    const int*   x      = (const int*)d_in[0];
    const float* emb    = (const float*)d_in[1];
    const float* attn_w = (const float*)d_in[2];
    const float* attn_b = (const float*)d_in[3];
    const float* ln_a   = (const float*)d_in[4];
    const float* ln_b   = (const float*)d_in[5];
    const float* w1     = (const float*)d_in[6];
    const float* b1     = (const float*)d_in[7];
    const float* w2     = (const float*)d_in[8];
    const float* b2     = (const float*)d_in[9];
    const float* na     = (const float*)d_in[10];
    const float* nb     = (const float*)d_in[11];
    float* out = (float*)d_out;

    float *h;
    f16 *qh, *qlo, *y, *o, *f;
    f16 *wq, *wo, *wf1, *wf2;
    cudaGetSymbolAddress((void**)&h, g_h);
    cudaGetSymbolAddress((void**)&qh, g_qkvh);
    cudaGetSymbolAddress((void**)&qlo, g_qkvl);
    cudaGetSymbolAddress((void**)&y, g_y);
    cudaGetSymbolAddress((void**)&o, g_o);
    cudaGetSymbolAddress((void**)&f, g_f);
    cudaGetSymbolAddress((void**)&wq, g_wqkv);
    cudaGetSymbolAddress((void**)&wo, g_wo);
    cudaGetSymbolAddress((void**)&wf1, g_w1);
    cudaGetSymbolAddress((void**)&wf2, g_w2);

    cudaFuncSetAttribute(tgemm_k<0>, cudaFuncAttributeMaxDynamicSharedMemorySize, GEMM_SMEM);
    cudaFuncSetAttribute(tgemm_k<1>, cudaFuncAttributeMaxDynamicSharedMemorySize, GEMM_SMEM);
    cudaFuncSetAttribute(tgemm_k<2>, cudaFuncAttributeMaxDynamicSharedMemorySize, GEMM_SMEM);
    cudaFuncSetAttribute(flash_k, cudaFuncAttributeMaxDynamicSharedMemorySize, FL_SMEM);

    dim3 cb(32, 8);
    convt_all_k<<<LL * TILES_PER_LAYER, cb>>>(attn_w, w1, w2, wq, wo, wf1, wf2);
    embed_k<<<(MM * DD + 255) / 256, 256>>>(x, emb, h);

    dim3 gQKV(QKVN / 128, (MM + 127) / 128);   // (24, 32)
    dim3 gD(DD / 128, (MM + 127) / 128);       // (8, 32)
    dim3 gF(FF / 128, (MM + 127) / 128);       // (32, 32)
    dim3 gFA(8, BB * HH);

    for (int l = 0; l < LL; l++) {
        const float* Wb = attn_b + (size_t)l * 4 * DD;
        const float* la = ln_a + (size_t)l * 2 * DD;
        const float* lb = ln_b + (size_t)l * 2 * DD;

        // attention sublayer (launch #6 of the graph = tgemm<1> for ncu)
        ln_h_k<<<MM, 256>>>(h, la, lb, y);
        tgemm_k<0><<<gQKV, 256, GEMM_SMEM>>>(y,
            wq + (size_t)l*QKVN*DD, Wb, nullptr, qh, qlo, MM, QKVN, DD);
        flash_k<<<gFA, 128, FL_SMEM>>>(qh, qlo, o);
        tgemm_k<1><<<gD, 256, GEMM_SMEM>>>(o,
            wo + (size_t)l*DD*DD, Wb + 3*DD, h, nullptr, nullptr, MM, DD, DD);

        // feed-forward sublayer
        ln_h_k<<<MM, 256>>>(h, la + DD, lb + DD, y);
        tgemm_k<2><<<gF, 256, GEMM_SMEM>>>(y,
            wf1 + (size_t)l*FF*DD, b1 + (size_t)l*FF, nullptr, f, nullptr, MM, FF, DD);
        tgemm_k<1><<<gD, 256, GEMM_SMEM>>>(f,
            wf2 + (size_t)l*DD*FF, b2 + (size_t)l*DD, h, nullptr, nullptr, MM, DD, FF);
    }

    layernorm_k<<<MM, 256>>>(h, na, nb, out);
}